// round 4
// baseline (speedup 1.0000x reference)
#include <cuda_runtime.h>

// CrossNet: xi = x0; for l in 0..2: s = dot(xi, W[l]); xi = x0*s + B[l] + xi
// BATCH=16384, DIM=1024, ORDER=3, all float32.
// One CTA (256 threads) per row; each thread owns 4 floats (float4).
// xi held in registers across all 3 layers -> x0 read once, out written once.

#define BATCH 16384
#define DIM   1024
#define ORDER 3
#define TPB   256            // DIM/4 threads
#define VPT   (DIM / (4 * TPB))  // = 1 float4 per thread

__global__ __launch_bounds__(TPB, 8)
void crossnet_kernel(const float4* __restrict__ x0,
                     const float4* __restrict__ W,
                     const float4* __restrict__ B,
                     float4* __restrict__ out)
{
    const int row = blockIdx.x;
    const int t   = threadIdx.x;
    const int idx = row * (DIM / 4) + t;

    const float4 x  = x0[idx];
    float4       xi = x;

    __shared__ float red[TPB / 32];
    __shared__ float s_bcast;

    #pragma unroll
    for (int l = 0; l < ORDER; l++) {
        // partial dot(xi, W[l]) over this thread's 4 elements
        const float4 w = W[l * (DIM / 4) + t];
        float p = xi.x * w.x + xi.y * w.y + xi.z * w.z + xi.w * w.w;

        // warp tree-reduce
        #pragma unroll
        for (int o = 16; o > 0; o >>= 1)
            p += __shfl_xor_sync(0xffffffffu, p, o);

        const int wid = t >> 5;
        if ((t & 31) == 0) red[wid] = p;
        __syncthreads();

        // first 8 lanes reduce the 8 warp partials
        if (t < (TPB / 32)) {
            float v = red[t];
            #pragma unroll
            for (int o = (TPB / 64); o > 0; o >>= 1)
                v += __shfl_xor_sync(0xffu, v, o);
            if (t == 0) s_bcast = v;
        }
        __syncthreads();

        const float  s = s_bcast;
        const float4 b = B[l * (DIM / 4) + t];
        xi.x = fmaf(x.x, s, b.x + xi.x);
        xi.y = fmaf(x.y, s, b.y + xi.y);
        xi.z = fmaf(x.z, s, b.z + xi.z);
        xi.w = fmaf(x.w, s, b.w + xi.w);
    }

    out[idx] = xi;
}

extern "C" void kernel_launch(void* const* d_in, const int* in_sizes, int n_in,
                              void* d_out, int out_size)
{
    const float4* x0 = (const float4*)d_in[0];
    const float4* W  = (const float4*)d_in[1];
    const float4* B  = (const float4*)d_in[2];
    float4*       out = (float4*)d_out;

    crossnet_kernel<<<BATCH, TPB>>>(x0, W, B, out);
}

// round 7
// speedup vs baseline: 1.1212x; 1.1212x over previous
#include <cuda_runtime.h>

// CrossNet closed form:
//   xi = a_i * x0 + c_i,  c_i = sum_{l<i} B_l  (data-independent)
//   d_l = x0 . W_l ;  e_l = c_l . W_l (constants) ;
//   a_0 = 1 ;  a_{l+1} = a_l * (1 + d_l) + e_l   [e_0 = 0]
//   out = a_3 * x0 + (B0+B1+B2)
//
// Kernel 1 (1 CTA): e1, e2, Bsum  ->  __device__ globals.
// Kernel 2: R rows per CTA; W/Bsum pinned in registers; x0 read once,
// all three dots in one pass, ONE barrier per row (double-buffered smem).

#define BATCH 16384
#define DIM   1024
#define ORDER 3
#define TPB   256
#define D4    (DIM / 4)      // 256 float4 per row
#define R     8              // rows per CTA
#define GRID  (BATCH / R)

__device__ float  g_e1, g_e2;
__device__ float4 g_bsum[D4];

__device__ __forceinline__ float dot4(float4 a, float4 b) {
    return a.x * b.x + a.y * b.y + a.z * b.z + a.w * b.w;
}

__global__ void precompute_kernel(const float4* __restrict__ W,
                                  const float4* __restrict__ B)
{
    const int t = threadIdx.x;

    const float4 b0 = B[t];
    const float4 b1 = B[D4 + t];
    const float4 b2 = B[2 * D4 + t];
    const float4 w1 = W[D4 + t];
    const float4 w2 = W[2 * D4 + t];

    float4 bs;
    bs.x = b0.x + b1.x + b2.x;  bs.y = b0.y + b1.y + b2.y;
    bs.z = b0.z + b1.z + b2.z;  bs.w = b0.w + b1.w + b2.w;
    g_bsum[t] = bs;

    float4 c01;
    c01.x = b0.x + b1.x; c01.y = b0.y + b1.y;
    c01.z = b0.z + b1.z; c01.w = b0.w + b1.w;

    float p1 = dot4(b0, w1);     // e1 = B0 . W1
    float p2 = dot4(c01, w2);    // e2 = (B0+B1) . W2

    #pragma unroll
    for (int o = 16; o > 0; o >>= 1) {
        p1 += __shfl_xor_sync(0xffffffffu, p1, o);
        p2 += __shfl_xor_sync(0xffffffffu, p2, o);
    }

    __shared__ float red[8][2];
    if ((t & 31) == 0) { red[t >> 5][0] = p1; red[t >> 5][1] = p2; }
    __syncthreads();

    if (t == 0) {
        float e1 = 0.f, e2 = 0.f;
        #pragma unroll
        for (int w = 0; w < 8; w++) { e1 += red[w][0]; e2 += red[w][1]; }
        g_e1 = e1;
        g_e2 = e2;
    }
}

__global__ __launch_bounds__(TPB, 6)
void crossnet_main(const float4* __restrict__ x0,
                   const float4* __restrict__ W,
                   float4* __restrict__ out)
{
    const int t    = threadIdx.x;
    const int wid  = t >> 5;
    const int base = blockIdx.x * R;

    // Persistent per-thread state for this column group (4 cols at 4*t)
    const float4 w0 = W[t];
    const float4 w1 = W[D4 + t];
    const float4 w2 = W[2 * D4 + t];
    const float4 bs = g_bsum[t];
    const float  e1 = g_e1;
    const float  e2 = g_e2;

    __shared__ float red[2][8][3];   // double-buffered -> 1 barrier per row

    float4 x = x0[base * D4 + t];    // prefetch row 0

    #pragma unroll
    for (int r = 0; r < R; r++) {
        const float4 xc  = x;
        const int    idx = (base + r) * D4 + t;
        if (r + 1 < R) x = x0[idx + D4];   // prefetch next row early

        // three simultaneous partial dots of x0 with W0..W2
        float p0 = dot4(xc, w0);
        float p1 = dot4(xc, w1);
        float p2 = dot4(xc, w2);

        #pragma unroll
        for (int o = 16; o > 0; o >>= 1) {
            p0 += __shfl_xor_sync(0xffffffffu, p0, o);
            p1 += __shfl_xor_sync(0xffffffffu, p1, o);
            p2 += __shfl_xor_sync(0xffffffffu, p2, o);
        }

        const int buf = r & 1;
        if ((t & 31) == 0) {
            red[buf][wid][0] = p0;
            red[buf][wid][1] = p1;
            red[buf][wid][2] = p2;
        }
        __syncthreads();

        // every thread sums the 8 warp partials (broadcast LDS, consistent order)
        float d0 = 0.f, d1 = 0.f, d2 = 0.f;
        #pragma unroll
        for (int w = 0; w < 8; w++) {
            d0 += red[buf][w][0];
            d1 += red[buf][w][1];
            d2 += red[buf][w][2];
        }

        // scalar recurrence (redundant per thread; no second barrier needed:
        // next row writes the other buffer)
        const float a1 = 1.0f + d0;
        const float s1 = fmaf(a1, d1, e1);
        const float a2 = a1 + s1;
        const float s2 = fmaf(a2, d2, e2);
        const float a3 = a2 + s2;

        float4 o;
        o.x = fmaf(a3, xc.x, bs.x);
        o.y = fmaf(a3, xc.y, bs.y);
        o.z = fmaf(a3, xc.z, bs.z);
        o.w = fmaf(a3, xc.w, bs.w);
        out[idx] = o;
    }
}

extern "C" void kernel_launch(void* const* d_in, const int* in_sizes, int n_in,
                              void* d_out, int out_size)
{
    const float4* x0 = (const float4*)d_in[0];
    const float4* W  = (const float4*)d_in[1];
    const float4* B  = (const float4*)d_in[2];
    float4*       out = (float4*)d_out;

    precompute_kernel<<<1, TPB>>>(W, B);
    crossnet_main<<<GRID, TPB>>>(x0, W, out);
}

// round 9
// speedup vs baseline: 1.1298x; 1.0077x over previous
#include <cuda_runtime.h>

// CrossNet closed form, single fused persistent kernel.
//   xi = a_i*x0 + c_i,  c_i = sum_{l<i} B_l
//   d_l = x0.W_l ; e_l = c_l.W_l (row-independent)
//   a1 = 1+d0 ; a2 = a1 + (a1*d1+e1) ; a3 = a2 + (a2*d2+e2)
//   out = a3*x0 + (B0+B1+B2)
//
// Warp-per-row: 15 SHFL + 0 barriers per row (vs 120 SHFL + 2 BAR before).
// W staged in smem per CTA; bsum in per-lane registers; x0 read once.

#define BATCH 16384
#define DIM   1024
#define D4    (DIM / 4)     // 256 float4 per row
#define TPB   256
#define NWARP (TPB / 32)
#define GRID  296           // 2 CTAs per SM, single wave
#define TOTW  (GRID * NWARP)

__device__ __forceinline__ float dot4(float4 a, float4 b) {
    return a.x * b.x + a.y * b.y + a.z * b.z + a.w * b.w;
}

__global__ __launch_bounds__(TPB, 2)
void crossnet_fused(const float4* __restrict__ x0,
                    const float4* __restrict__ Wg,
                    const float4* __restrict__ Bg,
                    float4* __restrict__ out)
{
    __shared__ float4 ws0[D4], ws1[D4], ws2[D4], bsum_s[D4];
    __shared__ float  red[NWARP][2];
    __shared__ float  e_s[2];

    const int t    = threadIdx.x;
    const int lane = t & 31;
    const int wid  = t >> 5;

    // ---- prologue: stage W, compute bsum, e1, e2 (per-CTA, redundant) ----
    {
        const float4 w1 = Wg[D4 + t];
        const float4 w2 = Wg[2 * D4 + t];
        ws0[t] = Wg[t];
        ws1[t] = w1;
        ws2[t] = w2;

        const float4 b0 = Bg[t];
        const float4 b1 = Bg[D4 + t];
        const float4 b2 = Bg[2 * D4 + t];

        float4 c01, bs;
        c01.x = b0.x + b1.x; c01.y = b0.y + b1.y;
        c01.z = b0.z + b1.z; c01.w = b0.w + b1.w;
        bs.x = c01.x + b2.x; bs.y = c01.y + b2.y;
        bs.z = c01.z + b2.z; bs.w = c01.w + b2.w;
        bsum_s[t] = bs;

        float p1 = dot4(b0, w1);      // e1 = B0 . W1
        float p2 = dot4(c01, w2);     // e2 = (B0+B1) . W2
        #pragma unroll
        for (int o = 16; o > 0; o >>= 1) {
            p1 += __shfl_xor_sync(0xffffffffu, p1, o);
            p2 += __shfl_xor_sync(0xffffffffu, p2, o);
        }
        if (lane == 0) { red[wid][0] = p1; red[wid][1] = p2; }
    }
    __syncthreads();
    if (t == 0) {
        float e1 = 0.f, e2 = 0.f;
        #pragma unroll
        for (int w = 0; w < NWARP; w++) { e1 += red[w][0]; e2 += red[w][1]; }
        e_s[0] = e1;
        e_s[1] = e2;
    }
    __syncthreads();

    const float e1 = e_s[0];
    const float e2 = e_s[1];

    // hoist bsum for this lane's 8 column-chunks into registers (once)
    float4 bsp[8];
    #pragma unroll
    for (int i = 0; i < 8; i++) bsp[i] = bsum_s[i * 32 + lane];

    // ---- mainloop: warp-per-row, persistent grid-stride ----
    for (int row = blockIdx.x * NWARP + wid; row < BATCH; row += TOTW) {
        const float4* __restrict__ xr = x0 + (size_t)row * D4;

        float4 x[8];
        #pragma unroll
        for (int i = 0; i < 8; i++) x[i] = xr[i * 32 + lane];

        float p0 = 0.f, p1 = 0.f, p2 = 0.f;
        #pragma unroll
        for (int i = 0; i < 8; i++) {
            const int c = i * 32 + lane;
            p0 += dot4(x[i], ws0[c]);
            p1 += dot4(x[i], ws1[c]);
            p2 += dot4(x[i], ws2[c]);
        }

        #pragma unroll
        for (int o = 16; o > 0; o >>= 1) {
            p0 += __shfl_xor_sync(0xffffffffu, p0, o);
            p1 += __shfl_xor_sync(0xffffffffu, p1, o);
            p2 += __shfl_xor_sync(0xffffffffu, p2, o);
        }

        const float a1 = 1.0f + p0;
        const float s1 = fmaf(a1, p1, e1);
        const float a2 = a1 + s1;
        const float s2 = fmaf(a2, p2, e2);
        const float a3 = a2 + s2;

        float4* __restrict__ orow = out + (size_t)row * D4;
        #pragma unroll
        for (int i = 0; i < 8; i++) {
            float4 o;
            o.x = fmaf(a3, x[i].x, bsp[i].x);
            o.y = fmaf(a3, x[i].y, bsp[i].y);
            o.z = fmaf(a3, x[i].z, bsp[i].z);
            o.w = fmaf(a3, x[i].w, bsp[i].w);
            orow[i * 32 + lane] = o;
        }
    }
}

extern "C" void kernel_launch(void* const* d_in, const int* in_sizes, int n_in,
                              void* d_out, int out_size)
{
    const float4* x0 = (const float4*)d_in[0];
    const float4* W  = (const float4*)d_in[1];
    const float4* B  = (const float4*)d_in[2];
    float4*       out = (float4*)d_out;

    crossnet_fused<<<GRID, TPB>>>(x0, W, B, out);
}

// round 10
// speedup vs baseline: 1.4949x; 1.3232x over previous
#include <cuda_runtime.h>

// CrossNet closed form, fused persistent kernel, 2 rows per warp iteration.
//   d_l = x0.W_l ; e_l = (sum_{j<l} B_j).W_l (row-independent)
//   a1 = 1+d0 ; a2 = a1 + (a1*d1+e1) ; a3 = a2 + (a2*d2+e2)
//   out = a3*x0 + (B0+B1+B2)

#define BATCH 16384
#define DIM   1024
#define D4    (DIM / 4)     // 256 float4 per row
#define TPB   256
#define NWARP (TPB / 32)
#define GRID  296           // 2 CTAs/SM, single wave
#define TOTW  (GRID * NWARP)
#define RPI   2             // rows per warp iteration

__device__ __forceinline__ float dot4(float4 a, float4 b) {
    return a.x * b.x + a.y * b.y + a.z * b.z + a.w * b.w;
}

__global__ __launch_bounds__(TPB, 2)
void crossnet_fused(const float4* __restrict__ x0,
                    const float4* __restrict__ Wg,
                    const float4* __restrict__ Bg,
                    float4* __restrict__ out)
{
    __shared__ float4 ws0[D4], ws1[D4], ws2[D4], bsum_s[D4];
    __shared__ float  red[NWARP][2];
    __shared__ float  e_s[2];

    const int t    = threadIdx.x;
    const int lane = t & 31;
    const int wid  = t >> 5;

    // ---- prologue: stage W, compute bsum, e1, e2 ----
    {
        const float4 w1 = Wg[D4 + t];
        const float4 w2 = Wg[2 * D4 + t];
        ws0[t] = Wg[t];
        ws1[t] = w1;
        ws2[t] = w2;

        const float4 b0 = Bg[t];
        const float4 b1 = Bg[D4 + t];
        const float4 b2 = Bg[2 * D4 + t];

        float4 c01, bs;
        c01.x = b0.x + b1.x; c01.y = b0.y + b1.y;
        c01.z = b0.z + b1.z; c01.w = b0.w + b1.w;
        bs.x = c01.x + b2.x; bs.y = c01.y + b2.y;
        bs.z = c01.z + b2.z; bs.w = c01.w + b2.w;
        bsum_s[t] = bs;

        float p1 = dot4(b0, w1);      // e1 = B0 . W1
        float p2 = dot4(c01, w2);     // e2 = (B0+B1) . W2
        #pragma unroll
        for (int o = 16; o > 0; o >>= 1) {
            p1 += __shfl_xor_sync(0xffffffffu, p1, o);
            p2 += __shfl_xor_sync(0xffffffffu, p2, o);
        }
        if (lane == 0) { red[wid][0] = p1; red[wid][1] = p2; }
    }
    __syncthreads();
    if (t == 0) {
        float e1 = 0.f, e2 = 0.f;
        #pragma unroll
        for (int w = 0; w < NWARP; w++) { e1 += red[w][0]; e2 += red[w][1]; }
        e_s[0] = e1;
        e_s[1] = e2;
    }
    __syncthreads();

    const float e1 = e_s[0];
    const float e2 = e_s[1];

    // ---- mainloop: 2 rows per warp iteration, persistent grid-stride ----
    for (int row = (blockIdx.x * NWARP + wid) * RPI; row < BATCH;
         row += TOTW * RPI)
    {
        const float4* __restrict__ xrA = x0 + (size_t)row * D4;
        const float4* __restrict__ xrB = xrA + D4;

        // 16 streaming loads issued up front (2x MLP vs 1 row)
        float4 xA[8], xB[8];
        #pragma unroll
        for (int i = 0; i < 8; i++) xA[i] = __ldcs(&xrA[i * 32 + lane]);
        #pragma unroll
        for (int i = 0; i < 8; i++) xB[i] = __ldcs(&xrB[i * 32 + lane]);

        // 6 partial dots; each W chunk loaded once, used for both rows
        float a0 = 0.f, a1p = 0.f, a2p = 0.f;
        float b0 = 0.f, b1p = 0.f, b2p = 0.f;
        #pragma unroll
        for (int i = 0; i < 8; i++) {
            const int c = i * 32 + lane;
            const float4 w0 = ws0[c];
            const float4 w1 = ws1[c];
            const float4 w2 = ws2[c];
            a0  += dot4(xA[i], w0);
            a1p += dot4(xA[i], w1);
            a2p += dot4(xA[i], w2);
            b0  += dot4(xB[i], w0);
            b1p += dot4(xB[i], w1);
            b2p += dot4(xB[i], w2);
        }

        // 6 independent shuffle chains pipeline through 5 levels
        #pragma unroll
        for (int o = 16; o > 0; o >>= 1) {
            a0  += __shfl_xor_sync(0xffffffffu, a0,  o);
            b0  += __shfl_xor_sync(0xffffffffu, b0,  o);
            a1p += __shfl_xor_sync(0xffffffffu, a1p, o);
            b1p += __shfl_xor_sync(0xffffffffu, b1p, o);
            a2p += __shfl_xor_sync(0xffffffffu, a2p, o);
            b2p += __shfl_xor_sync(0xffffffffu, b2p, o);
        }

        const float aA1 = 1.0f + a0;
        const float sA1 = fmaf(aA1, a1p, e1);
        const float aA2 = aA1 + sA1;
        const float sA2 = fmaf(aA2, a2p, e2);
        const float aA3 = aA2 + sA2;

        const float aB1 = 1.0f + b0;
        const float sB1 = fmaf(aB1, b1p, e1);
        const float aB2 = aB1 + sB1;
        const float sB2 = fmaf(aB2, b2p, e2);
        const float aB3 = aB2 + sB2;

        float4* __restrict__ orA = out + (size_t)row * D4;
        float4* __restrict__ orB = orA + D4;
        #pragma unroll
        for (int i = 0; i < 8; i++) {
            const int c = i * 32 + lane;
            const float4 bs = bsum_s[c];   // from smem: frees 32 regs
            float4 oA, oB;
            oA.x = fmaf(aA3, xA[i].x, bs.x);
            oA.y = fmaf(aA3, xA[i].y, bs.y);
            oA.z = fmaf(aA3, xA[i].z, bs.z);
            oA.w = fmaf(aA3, xA[i].w, bs.w);
            oB.x = fmaf(aB3, xB[i].x, bs.x);
            oB.y = fmaf(aB3, xB[i].y, bs.y);
            oB.z = fmaf(aB3, xB[i].z, bs.z);
            oB.w = fmaf(aB3, xB[i].w, bs.w);
            __stcs(&orA[c], oA);
            __stcs(&orB[c], oB);
        }
    }
}

extern "C" void kernel_launch(void* const* d_in, const int* in_sizes, int n_in,
                              void* d_out, int out_size)
{
    const float4* x0 = (const float4*)d_in[0];
    const float4* W  = (const float4*)d_in[1];
    const float4* B  = (const float4*)d_in[2];
    float4*       out = (float4*)d_out;

    crossnet_fused<<<GRID, TPB>>>(x0, W, B, out);
}

// round 15
// speedup vs baseline: 1.4987x; 1.0026x over previous
#include <cuda_runtime.h>

// CrossNet closed form, fused persistent kernel.
//   d_l = x0.W_l ; e_l = (sum_{j<l} B_j).W_l (row-independent)
//   a1 = 1+d0 ; a2 = a1 + (a1*d1+e1) ; a3 = a2 + (a2*d2+e2)
//   out = a3*x0 + (B0+B1+B2)
//
// R10->R11: x no longer held in registers across the iteration. Dots consume
// x transiently (L1-allocating loads); epilogue re-reads x via __ldcg (L2 hit).
// Frees ~64 regs -> 3 CTAs/SM (24 warps) -> more MLP + makespan 4->3 pairs.

#define BATCH 16384
#define DIM   1024
#define D4    (DIM / 4)     // 256 float4 per row
#define TPB   256
#define NWARP (TPB / 32)
#define OCC   3             // CTAs per SM
#define GRID  (148 * OCC)   // 444, single persistent wave
#define TOTW  (GRID * NWARP)
#define NPAIR (BATCH / 2)

__device__ __forceinline__ float dot4(float4 a, float4 b) {
    return a.x * b.x + a.y * b.y + a.z * b.z + a.w * b.w;
}

__global__ __launch_bounds__(TPB, OCC)
void crossnet_fused(const float4* __restrict__ x0,
                    const float4* __restrict__ Wg,
                    const float4* __restrict__ Bg,
                    float4* __restrict__ out)
{
    __shared__ float4 ws0[D4], ws1[D4], ws2[D4], bsum_s[D4];
    __shared__ float  red[NWARP][2];
    __shared__ float  e_s[2];

    const int t    = threadIdx.x;
    const int lane = t & 31;
    const int wid  = t >> 5;

    // ---- prologue: stage W, compute bsum, e1, e2 ----
    {
        const float4 w1 = Wg[D4 + t];
        const float4 w2 = Wg[2 * D4 + t];
        ws0[t] = Wg[t];
        ws1[t] = w1;
        ws2[t] = w2;

        const float4 b0 = Bg[t];
        const float4 b1 = Bg[D4 + t];
        const float4 b2 = Bg[2 * D4 + t];

        float4 c01, bs;
        c01.x = b0.x + b1.x; c01.y = b0.y + b1.y;
        c01.z = b0.z + b1.z; c01.w = b0.w + b1.w;
        bs.x = c01.x + b2.x; bs.y = c01.y + b2.y;
        bs.z = c01.z + b2.z; bs.w = c01.w + b2.w;
        bsum_s[t] = bs;

        float p1 = dot4(b0, w1);      // e1 = B0 . W1
        float p2 = dot4(c01, w2);     // e2 = (B0+B1) . W2
        #pragma unroll
        for (int o = 16; o > 0; o >>= 1) {
            p1 += __shfl_xor_sync(0xffffffffu, p1, o);
            p2 += __shfl_xor_sync(0xffffffffu, p2, o);
        }
        if (lane == 0) { red[wid][0] = p1; red[wid][1] = p2; }
    }
    __syncthreads();
    if (t == 0) {
        float e1 = 0.f, e2 = 0.f;
        #pragma unroll
        for (int w = 0; w < NWARP; w++) { e1 += red[w][0]; e2 += red[w][1]; }
        e_s[0] = e1;
        e_s[1] = e2;
    }
    __syncthreads();

    const float e1 = e_s[0];
    const float e2 = e_s[1];

    // ---- mainloop: one row-pair per warp iteration, persistent grid-stride ----
    for (int pr = blockIdx.x * NWARP + wid; pr < NPAIR; pr += TOTW) {
        const float4* __restrict__ xrA = x0 + (size_t)(2 * pr) * D4;
        const float4* __restrict__ xrB = xrA + D4;

        // dots: x consumed transiently (not held across the iteration)
        float a0 = 0.f, a1p = 0.f, a2p = 0.f;
        float b0 = 0.f, b1p = 0.f, b2p = 0.f;
        #pragma unroll
        for (int i = 0; i < 8; i++) {
            const int c = i * 32 + lane;
            const float4 xA = xrA[c];
            const float4 xB = xrB[c];
            const float4 w0 = ws0[c];
            const float4 w1 = ws1[c];
            const float4 w2 = ws2[c];
            a0  += dot4(xA, w0);
            a1p += dot4(xA, w1);
            a2p += dot4(xA, w2);
            b0  += dot4(xB, w0);
            b1p += dot4(xB, w1);
            b2p += dot4(xB, w2);
        }

        // 6 independent shuffle chains pipeline through 5 levels
        #pragma unroll
        for (int o = 16; o > 0; o >>= 1) {
            a0  += __shfl_xor_sync(0xffffffffu, a0,  o);
            b0  += __shfl_xor_sync(0xffffffffu, b0,  o);
            a1p += __shfl_xor_sync(0xffffffffu, a1p, o);
            b1p += __shfl_xor_sync(0xffffffffu, b1p, o);
            a2p += __shfl_xor_sync(0xffffffffu, a2p, o);
            b2p += __shfl_xor_sync(0xffffffffu, b2p, o);
        }

        const float aA1 = 1.0f + a0;
        const float sA1 = fmaf(aA1, a1p, e1);
        const float aA2 = aA1 + sA1;
        const float sA2 = fmaf(aA2, a2p, e2);
        const float aA3 = aA2 + sA2;

        const float aB1 = 1.0f + b0;
        const float sB1 = fmaf(aB1, b1p, e1);
        const float aB2 = aB1 + sB1;
        const float sB2 = fmaf(aB2, b2p, e2);
        const float aB3 = aB2 + sB2;

        // epilogue: re-read x from L2 (__ldcg, no CSE with the dot-loop loads)
        float4* __restrict__ orA = out + (size_t)(2 * pr) * D4;
        float4* __restrict__ orB = orA + D4;
        #pragma unroll
        for (int i = 0; i < 8; i++) {
            const int c = i * 32 + lane;
            const float4 xA = __ldcg(&xrA[c]);
            const float4 xB = __ldcg(&xrB[c]);
            const float4 bs = bsum_s[c];
            float4 oA, oB;
            oA.x = fmaf(aA3, xA.x, bs.x);
            oA.y = fmaf(aA3, xA.y, bs.y);
            oA.z = fmaf(aA3, xA.z, bs.z);
            oA.w = fmaf(aA3, xA.w, bs.w);
            oB.x = fmaf(aB3, xB.x, bs.x);
            oB.y = fmaf(aB3, xB.y, bs.y);
            oB.z = fmaf(aB3, xB.z, bs.z);
            oB.w = fmaf(aB3, xB.w, bs.w);
            __stcs(&orA[c], oA);
            __stcs(&orB[c], oB);
        }
    }
}

extern "C" void kernel_launch(void* const* d_in, const int* in_sizes, int n_in,
                              void* d_out, int out_size)
{
    const float4* x0 = (const float4*)d_in[0];
    const float4* W  = (const float4*)d_in[1];
    const float4* B  = (const float4*)d_in[2];
    float4*       out = (float4*)d_out;

    crossnet_fused<<<GRID, TPB>>>(x0, W, B, out);
}